// round 5
// baseline (speedup 1.0000x reference)
#include <cuda_runtime.h>

#define DIM     128
#define NCLS    50
#define PAIRS   25
#define WPITCH  384
#define PPITCH  64
#define NMAX    50000

typedef unsigned long long ull;

__device__ float g_P[NMAX * PPITCH];
__device__ float g_Q[NMAX * PPITCH];
__device__ int   g_idx64;

// ---- packed f32x2 helpers ----------------------------------------------
__device__ __forceinline__ ull fma2(ull a, ull b, ull c) {
    ull d;
    asm("fma.rn.f32x2 %0, %1, %2, %3;" : "=l"(d) : "l"(a), "l"(b), "l"(c));
    return d;
}
__device__ __forceinline__ ull add2(ull a, ull b) {
    ull d;
    asm("add.rn.f32x2 %0, %1, %2;" : "=l"(d) : "l"(a), "l"(b));
    return d;
}
__device__ __forceinline__ ull dup2(float x) {
    ull d; unsigned int u = __float_as_uint(x);
    asm("mov.b64 %0, {%1, %1};" : "=l"(d) : "r"(u));
    return d;
}

// ==========================================================================
// Node kernel: 320 threads = 10 warps. Warps 0-4 compute P pairs 5w..5w+4,
// warps 5-9 compute Q pairs. Block covers 128 nodes; lane owns nodes
// l, l+32, l+64, l+96. h staged at pitch 33 (conflict-free scalar LDS).
// smem: wS ull[2][128][25] = 51200 B @0 (epilogue sOut overlays it)
//       hS float[128][33]  = 16896 B @51200
// ==========================================================================
#define NODE_T    320
#define NODE_SMEM (51200 + 16896)

__global__ __launch_bounds__(NODE_T, 2)
void node_kernel(const float* __restrict__ h,
                 const float* __restrict__ W,
                 const float* __restrict__ b,
                 const void*  __restrict__ src,
                 int N, int E)
{
    extern __shared__ __align__(16) char sm[];
    ull*   wS = (ull*)sm;                   // [half*128 + k][25]
    float* hS = (float*)(sm + 51200);       // [node][33]

    const int tid = threadIdx.x;
    const int w   = tid >> 5;
    const int l   = tid & 31;

    if (blockIdx.x == 0 && tid == 0) {
        const unsigned int* a = (const unsigned int*)src;
        int n = E < 256 ? E : 256;
        int all_hi_zero = 1;
        for (int i = 0; i < n; i++)
            if (a[2 * i + 1] != 0u) { all_hi_zero = 0; break; }
        g_idx64 = all_hi_zero;
    }

    // load W1 (half 0) and W2 (half 1) packed as class-pair ulls
    for (int i = tid; i < 2 * DIM * PAIRS; i += NODE_T) {
        int half = i / (DIM * PAIRS);
        int r = i % (DIM * PAIRS);
        int k = r / PAIRS, c = r % PAIRS;
        float2 v = make_float2(W[(2 * c) * WPITCH + half * DIM + k],
                               W[(2 * c + 1) * WPITCH + half * DIM + k]);
        ((float2*)wS)[(half * DIM + k) * PAIRS + c] = v;
    }

    const int base = blockIdx.x * 128;
    const int isP   = (w < 5);
    const int pbase = (isP ? w : w - 5) * 5;
    const ull* wkb  = wS + (isP ? 0 : DIM * PAIRS) * 1;  // half offset in k-rows
    const ull* wk0  = isP ? wS : (wS + DIM * PAIRS);
    (void)wkb;

    ull acc[4][5];
    const ull* b2 = (const ull*)b;
#pragma unroll
    for (int g = 0; g < 4; g++)
#pragma unroll
        for (int c = 0; c < 5; c++)
            acc[g][c] = isP ? b2[pbase + c] : 0ull;

#pragma unroll 1
    for (int ch = 0; ch < 4; ch++) {
        __syncthreads();
        for (int i = tid; i < 128 * 8; i += NODE_T) {
            int m = i >> 3, c4 = i & 7;
            int gn = base + m; if (gn >= N) gn = N - 1;
            float4 v = *(const float4*)(h + (size_t)gn * DIM + ch * 32 + c4 * 4);
            float* p = hS + m * 33 + c4 * 4;
            p[0] = v.x; p[1] = v.y; p[2] = v.z; p[3] = v.w;
        }
        __syncthreads();

#pragma unroll 2
        for (int kq = 0; kq < 32; kq++) {
            ull a[4];
#pragma unroll
            for (int g = 0; g < 4; g++)
                a[g] = dup2(hS[(l + 32 * g) * 33 + kq]);
            const ull* wr = wk0 + (ch * 32 + kq) * PAIRS + pbase;
#pragma unroll
            for (int c = 0; c < 5; c++) {
                ull wv = wr[c];
#pragma unroll
                for (int g = 0; g < 4; g++)
                    acc[g][c] = fma2(a[g], wv, acc[g][c]);
            }
        }
    }

    // epilogue: overlay wS with sOut[2][128][25]
    __syncthreads();
    ull* sOut = wS;
    const int half = isP ? 0 : 1;
#pragma unroll
    for (int g = 0; g < 4; g++)
#pragma unroll
        for (int c = 0; c < 5; c++)
            sOut[(half * 128 + l + 32 * g) * PAIRS + pbase + c] = acc[g][c];
    __syncthreads();

    int rv = N - base; if (rv > 128) rv = 128;
    if (rv > 0) {
        for (int i = tid; i < rv * PAIRS; i += NODE_T) {
            int m = i / PAIRS, c = i - m * PAIRS;
            *(ull*)(g_P + (size_t)(base + m) * PPITCH + 2 * c) = sOut[m * PAIRS + c];
            *(ull*)(g_Q + (size_t)(base + m) * PPITCH + 2 * c) = sOut[(128 + m) * PAIRS + c];
        }
    }
}

// ==========================================================================
// Edge kernel: 160 threads = 5 warps; warp w owns class-pairs 5w..5w+4.
// Block covers 256 edges; lane owns edges l+32g, g=0..7.
// smem: wp ull[128][25] = 25600 @0
//       sS int[256] @25600, sD int[256] @26624
//       eS float[256][33] = 33792 @27648  (epilogue sOut[128][25] overlays)
// ==========================================================================
#define EBT       160
#define EDGE_SMEM (27648 + 33792)

__global__ __launch_bounds__(EBT, 3)
void edge_kernel(const float* __restrict__ efeat,
                 const void*  __restrict__ src,
                 const void*  __restrict__ dst,
                 const float* __restrict__ W,
                 float* __restrict__ out,
                 int E)
{
    extern __shared__ __align__(16) char sm[];
    ull*   wp = (ull*)sm;                   // [k][25]
    int*   sS = (int*)(sm + 25600);
    int*   sD = (int*)(sm + 26624);
    float* eS = (float*)(sm + 27648);       // [edge][33]

    const int tid = threadIdx.x;
    const int w   = tid >> 5;
    const int l   = tid & 31;
    const int base = blockIdx.x * 256;
    const int use64 = g_idx64;

    for (int i = tid; i < DIM * PAIRS; i += EBT) {
        int k = i / PAIRS, c = i - k * PAIRS;
        float2 v = make_float2(W[(2 * c) * WPITCH + 2 * DIM + k],
                               W[(2 * c + 1) * WPITCH + 2 * DIM + k]);
        ((float2*)wp)[k * PAIRS + c] = v;
    }
    for (int i = tid; i < 256; i += EBT) {
        long long g = base + i; if (g >= E) g = E - 1;
        int s, d;
        if (use64) {
            s = (int)((const long long*)src)[g];
            d = (int)((const long long*)dst)[g];
        } else {
            s = ((const int*)src)[g];
            d = ((const int*)dst)[g];
        }
        sS[i] = s; sD[i] = d;
    }

    ull acc[8][5];
#pragma unroll
    for (int g = 0; g < 8; g++)
#pragma unroll
        for (int c = 0; c < 5; c++) acc[g][c] = 0ull;

#pragma unroll 1
    for (int ch = 0; ch < 4; ch++) {
        __syncthreads();
        for (int i = tid; i < 256 * 8; i += EBT) {
            int m = i >> 3, c4 = i & 7;
            int ge = base + m; if (ge >= E) ge = E - 1;
            float4 v = *(const float4*)(efeat + (size_t)ge * DIM + ch * 32 + c4 * 4);
            float* p = eS + m * 33 + c4 * 4;
            p[0] = v.x; p[1] = v.y; p[2] = v.z; p[3] = v.w;
        }
        __syncthreads();

#pragma unroll 2
        for (int kq = 0; kq < 32; kq++) {
            ull a[8];
#pragma unroll
            for (int g = 0; g < 8; g++)
                a[g] = dup2(eS[(l + 32 * g) * 33 + kq]);
            const ull* wr = wp + (ch * 32 + kq) * PAIRS + w * 5;
#pragma unroll
            for (int c = 0; c < 5; c++) {
                ull wv = wr[c];
#pragma unroll
                for (int g = 0; g < 8; g++)
                    acc[g][c] = fma2(a[g], wv, acc[g][c]);
            }
        }
    }

    // ---- epilogue: two half-passes of 128 edges -------------------------
    ull* sOut = (ull*)eS;    // [128][25]

#pragma unroll 1
    for (int hf = 0; hf < 2; hf++) {
        __syncthreads();
#pragma unroll
        for (int g2 = 0; g2 < 4; g2++)
#pragma unroll
            for (int c = 0; c < 5; c++)
                sOut[(l + 32 * g2) * PAIRS + w * 5 + c] = acc[hf * 4 + g2][c];
        __syncthreads();

        int hb = base + hf * 128;
        int rv = E - hb; if (rv > 128) rv = 128;
        if (rv > 0) {
            for (int i = tid; i < rv * PAIRS; i += EBT) {
                int row = i / PAIRS, c = i - row * PAIRS;
                int ridx = hf * 128 + row;
                ull pv = *(const ull*)(g_P + (size_t)sS[ridx] * PPITCH + 2 * c);
                ull qv = *(const ull*)(g_Q + (size_t)sD[ridx] * PPITCH + 2 * c);
                *(ull*)(out + (size_t)(hb + row) * NCLS + 2 * c) =
                    add2(add2(pv, qv), sOut[i]);
            }
        }
    }
}

// --------------------------------------------------------------------------
extern "C" void kernel_launch(void* const* d_in, const int* in_sizes, int n_in,
                              void* d_out, int out_size)
{
    const float* h   = (const float*)d_in[0];
    const float* e   = (const float*)d_in[1];
    const void*  src = d_in[2];
    const void*  dst = d_in[3];
    const float* W   = (const float*)d_in[4];
    const float* b   = (const float*)d_in[5];

    int N = in_sizes[0] / DIM;   // 50000
    int E = in_sizes[1] / DIM;   // 500000
    if (N > NMAX) N = NMAX;

    cudaFuncSetAttribute(node_kernel, cudaFuncAttributeMaxDynamicSharedMemorySize, NODE_SMEM);
    cudaFuncSetAttribute(edge_kernel, cudaFuncAttributeMaxDynamicSharedMemorySize, EDGE_SMEM);

    node_kernel<<<(N + 127) / 128, NODE_T, NODE_SMEM>>>(h, W, b, src, N, E);
    edge_kernel<<<(E + 255) / 256, EBT, EDGE_SMEM>>>(e, src, dst, W, (float*)d_out, E);
}

// round 7
// speedup vs baseline: 1.3218x; 1.3218x over previous
#include <cuda_runtime.h>
#include <cuda_bf16.h>
#include <cstdint>

#define DIM     128
#define NCLS    50
#define PAIRS   25
#define WPITCH  384
#define PPITCH  64
#define NMAX    50000

typedef unsigned long long ull;
typedef unsigned int uint;

__device__ float g_P[NMAX * PPITCH];
__device__ float g_Q[NMAX * PPITCH];
__device__ int   g_idx64;

// B-operand images, [n][136] bf16 rows (pitch 272B), hi/lo split
__device__ __align__(16) unsigned short g_Be_hi[64 * 136];    // W3, 64 rows
__device__ __align__(16) unsigned short g_Be_lo[64 * 136];
__device__ __align__(16) unsigned short g_Bn_hi[104 * 136];   // [W1;W2]
__device__ __align__(16) unsigned short g_Bn_lo[104 * 136];

// ---------------- helpers -------------------------------------------------
__device__ __forceinline__ uint smem_u32(const void* p) {
    uint a;
    asm("{ .reg .u64 t; cvta.to.shared.u64 t, %1; cvt.u32.u64 %0, t; }"
        : "=r"(a) : "l"(p));
    return a;
}
__device__ __forceinline__ void ldsm_x4(uint r[4], uint addr) {
    asm volatile("ldmatrix.sync.aligned.m8n8.x4.shared.b16 {%0,%1,%2,%3}, [%4];"
        : "=r"(r[0]), "=r"(r[1]), "=r"(r[2]), "=r"(r[3]) : "r"(addr));
}
__device__ __forceinline__ void ldsm_x2(uint r[2], uint addr) {
    asm volatile("ldmatrix.sync.aligned.m8n8.x2.shared.b16 {%0,%1}, [%2];"
        : "=r"(r[0]), "=r"(r[1]) : "r"(addr));
}
__device__ __forceinline__ void mma16816(float* d, const uint* a, const uint* b) {
    asm volatile("mma.sync.aligned.m16n8k16.row.col.f32.bf16.bf16.f32 "
        "{%0,%1,%2,%3}, {%4,%5,%6,%7}, {%8,%9}, {%0,%1,%2,%3};"
        : "+f"(d[0]), "+f"(d[1]), "+f"(d[2]), "+f"(d[3])
        : "r"(a[0]), "r"(a[1]), "r"(a[2]), "r"(a[3]), "r"(b[0]), "r"(b[1]));
}
__device__ __forceinline__ ull add2(ull a, ull b) {
    ull d;
    asm("add.rn.f32x2 %0, %1, %2;" : "=l"(d) : "l"(a), "l"(b));
    return d;
}
__device__ __forceinline__ void split_bf16(float a, unsigned short& hi, unsigned short& lo) {
    __nv_bfloat16 bh = __float2bfloat16(a);
    float r = a - __bfloat162float(bh);
    __nv_bfloat16 bl = __float2bfloat16(r);
    hi = reinterpret_cast<unsigned short&>(bh);
    lo = reinterpret_cast<unsigned short&>(bl);
}
// split a float4 into packed hi(uint2 = 4 bf16) and lo(uint2)
__device__ __forceinline__ void split4(float4 v, uint2& hi, uint2& lo) {
    unsigned short h0, h1, h2, h3, l0, l1, l2, l3;
    split_bf16(v.x, h0, l0); split_bf16(v.y, h1, l1);
    split_bf16(v.z, h2, l2); split_bf16(v.w, h3, l3);
    hi = make_uint2((uint)h0 | ((uint)h1 << 16), (uint)h2 | ((uint)h3 << 16));
    lo = make_uint2((uint)l0 | ((uint)l1 << 16), (uint)l2 | ((uint)l3 << 16));
}

// ==========================================================================
// Setup: idx-width detect + build bf16 hi/lo B images.
// ==========================================================================
__global__ void setup_kernel(const float* __restrict__ W,
                             const void* __restrict__ src, int E)
{
    int tid = threadIdx.x + blockIdx.x * blockDim.x;
    if (tid == 0) {
        const uint* a = (const uint*)src;
        int n = E < 256 ? E : 256;
        int ok = 1;
        for (int i = 0; i < n; i++)
            if (a[2 * i + 1] != 0u) { ok = 0; break; }
        g_idx64 = ok;
    }
    for (int i = tid; i < 64 * 136; i += blockDim.x * gridDim.x) {
        int n = i / 136, k = i - n * 136;
        float v = (n < NCLS && k < DIM) ? W[n * WPITCH + 2 * DIM + k] : 0.0f;
        unsigned short h, l; split_bf16(v, h, l);
        g_Be_hi[i] = h; g_Be_lo[i] = l;
    }
    for (int i = tid; i < 104 * 136; i += blockDim.x * gridDim.x) {
        int n = i / 136, k = i - n * 136;
        float v = 0.0f;
        if (k < DIM) {
            if (n < NCLS)            v = W[n * WPITCH + k];
            else if (n < 2 * NCLS)   v = W[(n - NCLS) * WPITCH + DIM + k];
        }
        unsigned short h, l; split_bf16(v, h, l);
        g_Bn_hi[i] = h; g_Bn_lo[i] = l;
    }
}

// ==========================================================================
// Node kernel: 128 nodes/block, 128 threads (4 warps x 2 m-tiles).
// D[128,104] = h x [W1;W2]^T (3-split bf16 MMA). P=cols0-49(+b), Q=cols50-99.
// smem: A_hi 10240 @0, A_lo @10240, B_hi @20480 (28288), B_lo @48768 (end 77056)
// sOut overlays @0: 128 x 104 f32 = 53248.
// ==========================================================================
#define NODE_SMEM 77056
#define NT_N 13

__global__ __launch_bounds__(128, 2)
void node_kernel(const float* __restrict__ h, const float* __restrict__ b, int N)
{
    extern __shared__ __align__(16) char sb[];
    const uint ub = smem_u32(sb);
    const int tid = threadIdx.x;
    const int wid = tid >> 5;
    const int lane = tid & 31;
    const int base = blockIdx.x * 128;

    const uint A_HI = 0, A_LO = 10240, B_HI = 20480, B_LO = 48768;

    // copy B images (28288 B each = 1768 float4)
    for (int i = tid; i < 1768; i += 128) {
        ((float4*)(sb + B_HI))[i] = ((const float4*)g_Bn_hi)[i];
        ((float4*)(sb + B_LO))[i] = ((const float4*)g_Bn_lo)[i];
    }

    float acc[2][NT_N][4];
#pragma unroll
    for (int mt = 0; mt < 2; mt++)
#pragma unroll
        for (int nt = 0; nt < NT_N; nt++)
#pragma unroll
            for (int r = 0; r < 4; r++) acc[mt][nt][r] = 0.0f;

#pragma unroll 1
    for (int ch = 0; ch < 4; ch++) {
        __syncthreads();
        // stage A chunk: 128 nodes x 32 k (1024 float4)
#pragma unroll
        for (int it = 0; it < 8; it++) {
            int i = it * 128 + tid;
            int m = i >> 3, k4 = (i & 7) * 4;
            int gn = base + m; if (gn >= N) gn = N - 1;
            float4 v = *(const float4*)(h + (size_t)gn * DIM + ch * 32 + k4);
            uint2 hi, lo; split4(v, hi, lo);
            *(uint2*)(sb + A_HI + m * 80 + k4 * 2) = hi;
            *(uint2*)(sb + A_LO + m * 80 + k4 * 2) = lo;
        }
        __syncthreads();

#pragma unroll
        for (int kt = 0; kt < 2; kt++) {
            int ktg = ch * 2 + kt;
            uint ahi[2][4], alo[2][4];
#pragma unroll
            for (int mt = 0; mt < 2; mt++) {
                uint row = wid * 32 + mt * 16 + (lane & 15);
                uint off = row * 80 + (lane >> 4) * 16 + kt * 32;
                ldsm_x4(ahi[mt], ub + A_HI + off);
                ldsm_x4(alo[mt], ub + A_LO + off);
            }
#pragma unroll
            for (int nt = 0; nt < NT_N; nt++) {
                uint l = lane & 15;
                uint boff = (nt * 8 + (l & 7)) * 272 + ((l >> 3) & 1) * 16 + ktg * 32;
                uint bhi[2], blo[2];
                ldsm_x2(bhi, ub + B_HI + boff);
                ldsm_x2(blo, ub + B_LO + boff);
#pragma unroll
                for (int mt = 0; mt < 2; mt++) {
                    mma16816(acc[mt][nt], ahi[mt], bhi);
                    mma16816(acc[mt][nt], alo[mt], bhi);
                    mma16816(acc[mt][nt], ahi[mt], blo);
                }
            }
        }
    }

    // frags -> sOut [128][104] f32
    __syncthreads();
    float* sOutF = (float*)sb;
#pragma unroll
    for (int mt = 0; mt < 2; mt++) {
        int r0 = wid * 32 + mt * 16 + (lane >> 2);
        int c0 = 2 * (lane & 3);
#pragma unroll
        for (int nt = 0; nt < NT_N; nt++) {
            *(float2*)(sOutF + r0 * 104 + nt * 8 + c0) =
                make_float2(acc[mt][nt][0], acc[mt][nt][1]);
            *(float2*)(sOutF + (r0 + 8) * 104 + nt * 8 + c0) =
                make_float2(acc[mt][nt][2], acc[mt][nt][3]);
        }
    }
    __syncthreads();

    const ull* sOutU = (const ull*)sb;   // pitch 52 ull
    const ull* b2 = (const ull*)b;
    int rv = N - base; if (rv > 128) rv = 128;
    if (rv > 0) {
        for (int i = tid; i < rv * PAIRS; i += 128) {
            int m = i / PAIRS, c = i - m * PAIRS;
            *(ull*)(g_P + (size_t)(base + m) * PPITCH + 2 * c) =
                add2(sOutU[m * 52 + c], b2[c]);
            *(ull*)(g_Q + (size_t)(base + m) * PPITCH + 2 * c) =
                sOutU[m * 52 + 25 + c];
        }
    }
}

// ==========================================================================
// Edge kernel: 256 edges/block, 128 threads (4 warps x 4 m-tiles of 16).
// R[256,56] = e x W3^T (3-split bf16 MMA); epilogue fuses P/Q gather+store.
// smem: A_hi 20480 @0, A_lo @20480, B_hi @40960 (17408), B_lo @58368,
//       sS @75776, sD @76800 (end 77824). sOut overlays @0: 256x56 f32.
// ==========================================================================
#define EDGE_SMEM 77824
#define NT_E 7

__global__ __launch_bounds__(128, 2)
void edge_kernel(const float* __restrict__ efeat,
                 const void* __restrict__ src,
                 const void* __restrict__ dst,
                 float* __restrict__ out, int E)
{
    extern __shared__ __align__(16) char sb[];
    const uint ub = smem_u32(sb);
    const int tid = threadIdx.x;
    const int wid = tid >> 5;
    const int lane = tid & 31;
    const int base = blockIdx.x * 256;

    const uint A_HI = 0, A_LO = 20480, B_HI = 40960, B_LO = 58368;
    int* sS = (int*)(sb + 75776);
    int* sD = (int*)(sb + 76800);

    // copy B images (17408 B each = 1088 float4)
    for (int i = tid; i < 1088; i += 128) {
        ((float4*)(sb + B_HI))[i] = ((const float4*)g_Be_hi)[i];
        ((float4*)(sb + B_LO))[i] = ((const float4*)g_Be_lo)[i];
    }
    // indices
    const int use64 = g_idx64;
    for (int i = tid; i < 256; i += 128) {
        long long g = base + i; if (g >= E) g = E - 1;
        if (use64) {
            sS[i] = (int)((const long long*)src)[g];
            sD[i] = (int)((const long long*)dst)[g];
        } else {
            sS[i] = ((const int*)src)[g];
            sD[i] = ((const int*)dst)[g];
        }
    }

    float acc[4][NT_E][4];
#pragma unroll
    for (int mt = 0; mt < 4; mt++)
#pragma unroll
        for (int nt = 0; nt < NT_E; nt++)
#pragma unroll
            for (int r = 0; r < 4; r++) acc[mt][nt][r] = 0.0f;

#pragma unroll 1
    for (int ch = 0; ch < 4; ch++) {
        __syncthreads();
        // stage A chunk: 256 edges x 32 k (2048 float4)
#pragma unroll
        for (int it = 0; it < 16; it++) {
            int i = it * 128 + tid;
            int m = i >> 3, k4 = (i & 7) * 4;
            int ge = base + m; if (ge >= E) ge = E - 1;
            float4 v = *(const float4*)(efeat + (size_t)ge * DIM + ch * 32 + k4);
            uint2 hi, lo; split4(v, hi, lo);
            *(uint2*)(sb + A_HI + m * 80 + k4 * 2) = hi;
            *(uint2*)(sb + A_LO + m * 80 + k4 * 2) = lo;
        }
        __syncthreads();

#pragma unroll
        for (int kt = 0; kt < 2; kt++) {
            int ktg = ch * 2 + kt;
            uint ahi[4][4], alo[4][4];
#pragma unroll
            for (int mt = 0; mt < 4; mt++) {
                uint row = wid * 64 + mt * 16 + (lane & 15);
                uint off = row * 80 + (lane >> 4) * 16 + kt * 32;
                ldsm_x4(ahi[mt], ub + A_HI + off);
                ldsm_x4(alo[mt], ub + A_LO + off);
            }
#pragma unroll
            for (int nt = 0; nt < NT_E; nt++) {
                uint l = lane & 15;
                uint boff = (nt * 8 + (l & 7)) * 272 + ((l >> 3) & 1) * 16 + ktg * 32;
                uint bhi[2], blo[2];
                ldsm_x2(bhi, ub + B_HI + boff);
                ldsm_x2(blo, ub + B_LO + boff);
#pragma unroll
                for (int mt = 0; mt < 4; mt++) {
                    mma16816(acc[mt][nt], ahi[mt], bhi);
                    mma16816(acc[mt][nt], alo[mt], bhi);
                    mma16816(acc[mt][nt], ahi[mt], blo);
                }
            }
        }
    }

    // frags -> sOut [256][56] f32
    __syncthreads();
    float* sOutF = (float*)sb;
#pragma unroll
    for (int mt = 0; mt < 4; mt++) {
        int r0 = wid * 64 + mt * 16 + (lane >> 2);
        int c0 = 2 * (lane & 3);
#pragma unroll
        for (int nt = 0; nt < NT_E; nt++) {
            *(float2*)(sOutF + r0 * 56 + nt * 8 + c0) =
                make_float2(acc[mt][nt][0], acc[mt][nt][1]);
            *(float2*)(sOutF + (r0 + 8) * 56 + nt * 8 + c0) =
                make_float2(acc[mt][nt][2], acc[mt][nt][3]);
        }
    }
    __syncthreads();

    const ull* sOutU = (const ull*)sb;   // pitch 28 ull
    int rv = E - base; if (rv > 256) rv = 256;
    if (rv > 0) {
        for (int i = tid; i < rv * PAIRS; i += 128) {
            int row = i / PAIRS, c = i - row * PAIRS;
            ull pv = *(const ull*)(g_P + (size_t)sS[row] * PPITCH + 2 * c);
            ull qv = *(const ull*)(g_Q + (size_t)sD[row] * PPITCH + 2 * c);
            *(ull*)(out + (size_t)(base + row) * NCLS + 2 * c) =
                add2(add2(pv, qv), sOutU[row * 28 + c]);
        }
    }
}

// --------------------------------------------------------------------------
extern "C" void kernel_launch(void* const* d_in, const int* in_sizes, int n_in,
                              void* d_out, int out_size)
{
    const float* h   = (const float*)d_in[0];
    const float* e   = (const float*)d_in[1];
    const void*  src = d_in[2];
    const void*  dst = d_in[3];
    const float* W   = (const float*)d_in[4];
    const float* b   = (const float*)d_in[5];

    int N = in_sizes[0] / DIM;   // 50000
    int E = in_sizes[1] / DIM;   // 500000
    if (N > NMAX) N = NMAX;

    static int attr_done = 0;
    if (!attr_done) {
        cudaFuncSetAttribute(node_kernel, cudaFuncAttributeMaxDynamicSharedMemorySize, NODE_SMEM);
        cudaFuncSetAttribute(edge_kernel, cudaFuncAttributeMaxDynamicSharedMemorySize, EDGE_SMEM);
        attr_done = 1;
    }

    setup_kernel<<<8, 256>>>(W, src, E);
    node_kernel<<<(N + 127) / 128, 128, NODE_SMEM>>>(h, b, N);
    edge_kernel<<<(E + 255) / 256, 128, EDGE_SMEM>>>(e, src, dst, (float*)d_out, E);
}

// round 8
// speedup vs baseline: 1.9324x; 1.4620x over previous
#include <cuda_runtime.h>
#include <cuda_bf16.h>
#include <cstdint>

#define DIM     128
#define NCLS    50
#define PAIRS   25
#define WPITCH  384
#define PPITCH  64
#define NMAX    50000

typedef unsigned long long ull;
typedef unsigned int uint;

__device__ float g_P[NMAX * PPITCH];
__device__ float g_Q[NMAX * PPITCH];
__device__ int   g_idx64;

// B-operand images, [n][136] bf16 rows (pitch 272B), hi/lo split
__device__ __align__(16) unsigned short g_Be_hi[64 * 136];    // W3, 64 rows
__device__ __align__(16) unsigned short g_Be_lo[64 * 136];
__device__ __align__(16) unsigned short g_Bn_hi[104 * 136];   // [W1;W2]
__device__ __align__(16) unsigned short g_Bn_lo[104 * 136];

// ---------------- helpers -------------------------------------------------
__device__ __forceinline__ uint smem_u32(const void* p) {
    uint a;
    asm("{ .reg .u64 t; cvta.to.shared.u64 t, %1; cvt.u32.u64 %0, t; }"
        : "=r"(a) : "l"(p));
    return a;
}
__device__ __forceinline__ void ldsm_x4(uint r[4], uint addr) {
    asm volatile("ldmatrix.sync.aligned.m8n8.x4.shared.b16 {%0,%1,%2,%3}, [%4];"
        : "=r"(r[0]), "=r"(r[1]), "=r"(r[2]), "=r"(r[3]) : "r"(addr));
}
__device__ __forceinline__ void ldsm_x2(uint r[2], uint addr) {
    asm volatile("ldmatrix.sync.aligned.m8n8.x2.shared.b16 {%0,%1}, [%2];"
        : "=r"(r[0]), "=r"(r[1]) : "r"(addr));
}
__device__ __forceinline__ void mma16816(float* d, const uint* a, const uint* b) {
    asm volatile("mma.sync.aligned.m16n8k16.row.col.f32.bf16.bf16.f32 "
        "{%0,%1,%2,%3}, {%4,%5,%6,%7}, {%8,%9}, {%0,%1,%2,%3};"
        : "+f"(d[0]), "+f"(d[1]), "+f"(d[2]), "+f"(d[3])
        : "r"(a[0]), "r"(a[1]), "r"(a[2]), "r"(a[3]), "r"(b[0]), "r"(b[1]));
}
__device__ __forceinline__ ull add2(ull a, ull b) {
    ull d;
    asm("add.rn.f32x2 %0, %1, %2;" : "=l"(d) : "l"(a), "l"(b));
    return d;
}
__device__ __forceinline__ void split_bf16(float a, unsigned short& hi, unsigned short& lo) {
    __nv_bfloat16 bh = __float2bfloat16(a);
    float r = a - __bfloat162float(bh);
    __nv_bfloat16 bl = __float2bfloat16(r);
    hi = reinterpret_cast<unsigned short&>(bh);
    lo = reinterpret_cast<unsigned short&>(bl);
}
// fast packed split: float4 -> hi bf16x4 + lo bf16x4 (exact residual math)
__device__ __forceinline__ void split4(float4 v, uint2& hi, uint2& lo) {
    uint pk0, pk1, l0, l1;
    asm("cvt.rn.bf16x2.f32 %0, %1, %2;" : "=r"(pk0) : "f"(v.y), "f"(v.x));
    asm("cvt.rn.bf16x2.f32 %0, %1, %2;" : "=r"(pk1) : "f"(v.w), "f"(v.z));
    float rx = v.x - __uint_as_float(pk0 << 16);
    float ry = v.y - __uint_as_float(pk0 & 0xffff0000u);
    float rz = v.z - __uint_as_float(pk1 << 16);
    float rw = v.w - __uint_as_float(pk1 & 0xffff0000u);
    asm("cvt.rn.bf16x2.f32 %0, %1, %2;" : "=r"(l0) : "f"(ry), "f"(rx));
    asm("cvt.rn.bf16x2.f32 %0, %1, %2;" : "=r"(l1) : "f"(rw), "f"(rz));
    hi = make_uint2(pk0, pk1);
    lo = make_uint2(l0, l1);
}

// ==========================================================================
// Setup: idx-width detect + build bf16 hi/lo B images.
// ==========================================================================
__global__ void setup_kernel(const float* __restrict__ W,
                             const void* __restrict__ src, int E)
{
    int tid = threadIdx.x + blockIdx.x * blockDim.x;
    if (tid == 0) {
        const uint* a = (const uint*)src;
        int n = E < 256 ? E : 256;
        int ok = 1;
        for (int i = 0; i < n; i++)
            if (a[2 * i + 1] != 0u) { ok = 0; break; }
        g_idx64 = ok;
    }
    for (int i = tid; i < 64 * 136; i += blockDim.x * gridDim.x) {
        int n = i / 136, k = i - n * 136;
        float v = (n < NCLS && k < DIM) ? W[n * WPITCH + 2 * DIM + k] : 0.0f;
        unsigned short h, l; split_bf16(v, h, l);
        g_Be_hi[i] = h; g_Be_lo[i] = l;
    }
    for (int i = tid; i < 104 * 136; i += blockDim.x * gridDim.x) {
        int n = i / 136, k = i - n * 136;
        float v = 0.0f;
        if (k < DIM) {
            if (n < NCLS)            v = W[n * WPITCH + k];
            else if (n < 2 * NCLS)   v = W[(n - NCLS) * WPITCH + DIM + k];
        }
        unsigned short h, l; split_bf16(v, h, l);
        g_Bn_hi[i] = h; g_Bn_lo[i] = l;
    }
}

// ==========================================================================
// Node kernel: 128 nodes/block, 256 threads (8 warps x 1 m-tile of 16).
// D[128,104] = h x [W1;W2]^T (3-split bf16 MMA). P=cols0-49(+b), Q=cols50-99.
// smem: A_hi @0 (10240), A_lo @10240, B_hi @20480 (28288), B_lo @48768.
// sOut overlays @0: 128 x 104 f32.
// ==========================================================================
#define NODE_SMEM 77056
#define NT_N 13

__global__ __launch_bounds__(256, 2)
void node_kernel(const float* __restrict__ h, const float* __restrict__ b, int N)
{
    extern __shared__ __align__(16) char sb[];
    const uint ub = smem_u32(sb);
    const int tid = threadIdx.x;
    const int wid = tid >> 5;
    const int lane = tid & 31;
    const int base = blockIdx.x * 128;

    const uint A_HI = 0, A_LO = 10240, B_HI = 20480, B_LO = 48768;

    // copy B images (28288 B each = 1768 float4)
    for (int i = tid; i < 1768; i += 256) {
        ((float4*)(sb + B_HI))[i] = ((const float4*)g_Bn_hi)[i];
        ((float4*)(sb + B_LO))[i] = ((const float4*)g_Bn_lo)[i];
    }

    float acc[NT_N][4];
#pragma unroll
    for (int nt = 0; nt < NT_N; nt++)
#pragma unroll
        for (int r = 0; r < 4; r++) acc[nt][r] = 0.0f;

#pragma unroll 1
    for (int ch = 0; ch < 4; ch++) {
        __syncthreads();
        // stage A chunk: 128 nodes x 32 k (1024 float4)
#pragma unroll
        for (int it = 0; it < 4; it++) {
            int i = it * 256 + tid;
            int m = i >> 3, k4 = (i & 7) * 4;
            int gn = base + m; if (gn >= N) gn = N - 1;
            float4 v = *(const float4*)(h + (size_t)gn * DIM + ch * 32 + k4);
            uint2 hi, lo; split4(v, hi, lo);
            *(uint2*)(sb + A_HI + m * 80 + k4 * 2) = hi;
            *(uint2*)(sb + A_LO + m * 80 + k4 * 2) = lo;
        }
        __syncthreads();

#pragma unroll
        for (int kt = 0; kt < 2; kt++) {
            int ktg = ch * 2 + kt;
            uint ahi[4], alo[4];
            {
                uint row = wid * 16 + (lane & 15);
                uint off = row * 80 + (lane >> 4) * 16 + kt * 32;
                ldsm_x4(ahi, ub + A_HI + off);
                ldsm_x4(alo, ub + A_LO + off);
            }
#pragma unroll
            for (int nt = 0; nt < NT_N; nt++) {
                uint l = lane & 15;
                uint boff = (nt * 8 + (l & 7)) * 272 + ((l >> 3) & 1) * 16 + ktg * 32;
                uint bhi[2], blo[2];
                ldsm_x2(bhi, ub + B_HI + boff);
                ldsm_x2(blo, ub + B_LO + boff);
                mma16816(acc[nt], ahi, bhi);
                mma16816(acc[nt], alo, bhi);
                mma16816(acc[nt], ahi, blo);
            }
        }
    }

    // frags -> sOut [128][104] f32
    __syncthreads();
    float* sOutF = (float*)sb;
    {
        int r0 = wid * 16 + (lane >> 2);
        int c0 = 2 * (lane & 3);
#pragma unroll
        for (int nt = 0; nt < NT_N; nt++) {
            *(float2*)(sOutF + r0 * 104 + nt * 8 + c0) =
                make_float2(acc[nt][0], acc[nt][1]);
            *(float2*)(sOutF + (r0 + 8) * 104 + nt * 8 + c0) =
                make_float2(acc[nt][2], acc[nt][3]);
        }
    }
    __syncthreads();

    const ull* sOutU = (const ull*)sb;   // pitch 52 ull
    const ull* b2 = (const ull*)b;
    int rv = N - base; if (rv > 128) rv = 128;
    if (rv > 0) {
        for (int i = tid; i < rv * PAIRS; i += 256) {
            int m = i / PAIRS, c = i - m * PAIRS;
            *(ull*)(g_P + (size_t)(base + m) * PPITCH + 2 * c) =
                add2(sOutU[m * 52 + c], b2[c]);
            *(ull*)(g_Q + (size_t)(base + m) * PPITCH + 2 * c) =
                sOutU[m * 52 + 25 + c];
        }
    }
}

// ==========================================================================
// Edge kernel: 256 edges/block, 256 threads (8 warps x 2 m-tiles of 16).
// R[256,56] = e x W3^T (3-split bf16 MMA); epilogue fuses P/Q gather+store.
// smem: A_hi @0 (20480), A_lo @20480, B_hi @40960 (17408), B_lo @58368,
//       sS @75776, sD @76800 (end 77824). sOut overlays @0: 256x56 f32.
// ==========================================================================
#define EDGE_SMEM 77824
#define NT_E 7

__global__ __launch_bounds__(256, 2)
void edge_kernel(const float* __restrict__ efeat,
                 const void* __restrict__ src,
                 const void* __restrict__ dst,
                 float* __restrict__ out, int E)
{
    extern __shared__ __align__(16) char sb[];
    const uint ub = smem_u32(sb);
    const int tid = threadIdx.x;
    const int wid = tid >> 5;
    const int lane = tid & 31;
    const int base = blockIdx.x * 256;

    const uint A_HI = 0, A_LO = 20480, B_HI = 40960, B_LO = 58368;
    int* sS = (int*)(sb + 75776);
    int* sD = (int*)(sb + 76800);

    // copy B images (17408 B each = 1088 float4)
    for (int i = tid; i < 1088; i += 256) {
        ((float4*)(sb + B_HI))[i] = ((const float4*)g_Be_hi)[i];
        ((float4*)(sb + B_LO))[i] = ((const float4*)g_Be_lo)[i];
    }
    // indices
    const int use64 = g_idx64;
    {
        long long g = base + tid; if (g >= E) g = E - 1;
        if (use64) {
            sS[tid] = (int)((const long long*)src)[g];
            sD[tid] = (int)((const long long*)dst)[g];
        } else {
            sS[tid] = ((const int*)src)[g];
            sD[tid] = ((const int*)dst)[g];
        }
    }

    float acc[2][NT_E][4];
#pragma unroll
    for (int mt = 0; mt < 2; mt++)
#pragma unroll
        for (int nt = 0; nt < NT_E; nt++)
#pragma unroll
            for (int r = 0; r < 4; r++) acc[mt][nt][r] = 0.0f;

#pragma unroll 1
    for (int ch = 0; ch < 4; ch++) {
        __syncthreads();
        // stage A chunk: 256 edges x 32 k (2048 float4)
#pragma unroll
        for (int it = 0; it < 8; it++) {
            int i = it * 256 + tid;
            int m = i >> 3, k4 = (i & 7) * 4;
            int ge = base + m; if (ge >= E) ge = E - 1;
            float4 v = *(const float4*)(efeat + (size_t)ge * DIM + ch * 32 + k4);
            uint2 hi, lo; split4(v, hi, lo);
            *(uint2*)(sb + A_HI + m * 80 + k4 * 2) = hi;
            *(uint2*)(sb + A_LO + m * 80 + k4 * 2) = lo;
        }
        __syncthreads();

#pragma unroll
        for (int kt = 0; kt < 2; kt++) {
            int ktg = ch * 2 + kt;
            uint ahi[2][4], alo[2][4];
#pragma unroll
            for (int mt = 0; mt < 2; mt++) {
                uint row = wid * 32 + mt * 16 + (lane & 15);
                uint off = row * 80 + (lane >> 4) * 16 + kt * 32;
                ldsm_x4(ahi[mt], ub + A_HI + off);
                ldsm_x4(alo[mt], ub + A_LO + off);
            }
#pragma unroll
            for (int nt = 0; nt < NT_E; nt++) {
                uint l = lane & 15;
                uint boff = (nt * 8 + (l & 7)) * 272 + ((l >> 3) & 1) * 16 + ktg * 32;
                uint bhi[2], blo[2];
                ldsm_x2(bhi, ub + B_HI + boff);
                ldsm_x2(blo, ub + B_LO + boff);
#pragma unroll
                for (int mt = 0; mt < 2; mt++) {
                    mma16816(acc[mt][nt], ahi[mt], bhi);
                    mma16816(acc[mt][nt], alo[mt], bhi);
                    mma16816(acc[mt][nt], ahi[mt], blo);
                }
            }
        }
    }

    // frags -> sOut [256][56] f32
    __syncthreads();
    float* sOutF = (float*)sb;
#pragma unroll
    for (int mt = 0; mt < 2; mt++) {
        int r0 = wid * 32 + mt * 16 + (lane >> 2);
        int c0 = 2 * (lane & 3);
#pragma unroll
        for (int nt = 0; nt < NT_E; nt++) {
            *(float2*)(sOutF + r0 * 56 + nt * 8 + c0) =
                make_float2(acc[mt][nt][0], acc[mt][nt][1]);
            *(float2*)(sOutF + (r0 + 8) * 56 + nt * 8 + c0) =
                make_float2(acc[mt][nt][2], acc[mt][nt][3]);
        }
    }
    __syncthreads();

    const ull* sOutU = (const ull*)sb;   // pitch 28 ull
    int rv = E - base; if (rv > 256) rv = 256;
    if (rv > 0) {
        for (int i = tid; i < rv * PAIRS; i += 256) {
            int row = i / PAIRS, c = i - row * PAIRS;
            ull pv = *(const ull*)(g_P + (size_t)sS[row] * PPITCH + 2 * c);
            ull qv = *(const ull*)(g_Q + (size_t)sD[row] * PPITCH + 2 * c);
            *(ull*)(out + (size_t)(base + row) * NCLS + 2 * c) =
                add2(add2(pv, qv), sOutU[row * 28 + c]);
        }
    }
}

// --------------------------------------------------------------------------
extern "C" void kernel_launch(void* const* d_in, const int* in_sizes, int n_in,
                              void* d_out, int out_size)
{
    const float* h   = (const float*)d_in[0];
    const float* e   = (const float*)d_in[1];
    const void*  src = d_in[2];
    const void*  dst = d_in[3];
    const float* W   = (const float*)d_in[4];
    const float* b   = (const float*)d_in[5];

    int N = in_sizes[0] / DIM;   // 50000
    int E = in_sizes[1] / DIM;   // 500000
    if (N > NMAX) N = NMAX;

    static int attr_done = 0;
    if (!attr_done) {
        cudaFuncSetAttribute(node_kernel, cudaFuncAttributeMaxDynamicSharedMemorySize, NODE_SMEM);
        cudaFuncSetAttribute(edge_kernel, cudaFuncAttributeMaxDynamicSharedMemorySize, EDGE_SMEM);
        attr_done = 1;
    }

    setup_kernel<<<8, 256>>>(W, src, E);
    node_kernel<<<(N + 127) / 128, 256, NODE_SMEM>>>(h, b, N);
    edge_kernel<<<(E + 255) / 256, 256, EDGE_SMEM>>>(e, src, dst, (float*)d_out, E);
}